// round 13
// baseline (speedup 1.0000x reference)
#include <cuda_runtime.h>
#include <math.h>

// Problem constants
#define NB 64
#define CC 384
#define LL 3136      // 56*56
#define MM 16
#define DD 384
#define L4 784       // LL/4 (float4 per lf row)
#define SCH 4        // l-chunks per n
#define CHL 784      // l per chunk
#define CH4 196      // float4 per chunk

// Scratch (static device memory — no allocations)
__device__ float g_q[NB*MM*CC];            // scaled q, [n][m][c]
__device__ float g_fpart[SCH*NB*MM*CC];    // unnormalized partial fusion [ch][n][m][c]
__device__ float g_spart[SCH*NB*MM];       // partial exp-sums [ch][n][m]

// ---- f32x2 packed-FMA primitives (sm_100+) ----------------------------------
#define PACK2(d, xx, yy) \
    asm("mov.b64 %0, {%1, %2};" : "=l"(d) : "r"(__float_as_uint(xx)), "r"(__float_as_uint(yy)))
#define FMA2(d, a, b) \
    asm("fma.rn.f32x2 %0, %1, %2, %0;" : "+l"(d) : "l"(a), "l"(b))
#define UNPACK2(xx, yy, d) \
    asm("mov.b64 {%0, %1}, %2;" : "=r"(xx), "=r"(yy) : "l"(d))

// ---------------------------------------------------------------------------
// Kernel 0: q[n,m,c] = scale * (sum_d x[n,m,d]*Wq[c,d] + bq[c])
// ---------------------------------------------------------------------------
__global__ __launch_bounds__(256) void k_q(const float* __restrict__ x,
                                           const float* __restrict__ Wq,
                                           const float* __restrict__ bq) {
    const int n    = blockIdx.y;
    const int cblk = blockIdx.x * 32;
    const int tid  = threadIdx.x;
    const int warp = tid >> 5, lane = tid & 31;

    __shared__ float x_s[MM*DD];
    for (int j = tid; j < MM*DD; j += 256) x_s[j] = x[n*MM*DD + j];
    __syncthreads();
    const float4* xs4 = reinterpret_cast<const float4*>(x_s);
    const float scale = 0.05103103630798287f;   // 384^-0.5

    for (int cc = 0; cc < 4; ++cc) {
        const int c = cblk + warp*4 + cc;
        const float4* wrow = reinterpret_cast<const float4*>(Wq + (size_t)c*DD);
        float acc[MM];
        #pragma unroll
        for (int m = 0; m < MM; ++m) acc[m] = 0.f;
        #pragma unroll
        for (int s = 0; s < 3; ++s) {
            const int d4 = s*32 + lane;
            const float4 wv = wrow[d4];
            #pragma unroll
            for (int m = 0; m < MM; ++m) {
                const float4 xv = xs4[m*96 + d4];
                acc[m] += wv.x*xv.x + wv.y*xv.y + wv.z*xv.z + wv.w*xv.w;
            }
        }
        #pragma unroll
        for (int m = 0; m < MM; ++m) {
            #pragma unroll
            for (int off = 16; off; off >>= 1)
                acc[m] += __shfl_xor_sync(0xffffffffu, acc[m], off);
        }
        if (lane == 0) {
            const float b = bq[c];
            #pragma unroll
            for (int m = 0; m < MM; ++m)
                g_q[n*MM*CC + m*CC + c] = scale * (acc[m] + b);
        }
    }
}

// ---------------------------------------------------------------------------
// Fused attention kernel: per (chunk, n) CTA.
//  Phase 1: p_s[m][l] = exp( sum_c q[m,c]*lf[c,l] )  (FFMA2 over m-pairs)
//  Sums:    g_spart[ch][n][m] = sum_l p_s[m][l]      (deterministic)
//  Phase 2: g_fpart[ch][n][m][c] = sum_l p_s[m][l]*lf[c,l]  (FFMA2 over l-pairs)
// grid (SCH=4, 64), 256 threads, occ 2 => all 256 CTAs resident.
// ---------------------------------------------------------------------------
__global__ __launch_bounds__(256, 2) void k_attn(const float* __restrict__ lf) {
    extern __shared__ float smem[];
    float* p_s = smem;                 // [MM][CHL]  = 12544 floats (49 KB)
    float* q_t = smem + MM*CHL;        // [CC][MM]   =  6144 floats (24 KB)

    const int n    = blockIdx.y;
    const int ch   = blockIdx.x;
    const int tid  = threadIdx.x;
    const int warp = tid >> 5, lane = tid & 31;

    // stage q transposed: q_t[c][m]
    for (int j = tid; j < MM*CC; j += 256) {
        const int m = j / CC, c = j % CC;
        q_t[c*MM + m] = g_q[n*MM*CC + j];
    }
    __syncthreads();

    const float4* lf4 = reinterpret_cast<const float4*>(lf)
                        + (size_t)n*CC*L4 + ch*CH4;
    float4* p_s4 = reinterpret_cast<float4*>(p_s);

    // ---------------- phase 1: scores + exp into smem ----------------
    if (tid < CH4) {
        const ulonglong2* qt8 = reinterpret_cast<const ulonglong2*>(q_t);
        // acc[mp*4+lj]: f32x2 = (m=2mp, m=2mp+1) for l = 4*tid+lj
        unsigned long long acc[32];
        #pragma unroll
        for (int i = 0; i < 32; ++i) acc[i] = 0ull;

        #pragma unroll 2
        for (int c = 0; c < CC; ++c) {
            const float4 v = lf4[(size_t)c*L4 + tid];
            unsigned long long d0, d1, d2, d3;
            PACK2(d0, v.x, v.x); PACK2(d1, v.y, v.y);
            PACK2(d2, v.z, v.z); PACK2(d3, v.w, v.w);
            #pragma unroll
            for (int g = 0; g < 4; ++g) {
                const ulonglong2 qp = qt8[c*4 + g];  // .x=(m4g,4g+1) .y=(4g+2,4g+3)
                FMA2(acc[(2*g  )*4 + 0], qp.x, d0);
                FMA2(acc[(2*g  )*4 + 1], qp.x, d1);
                FMA2(acc[(2*g  )*4 + 2], qp.x, d2);
                FMA2(acc[(2*g  )*4 + 3], qp.x, d3);
                FMA2(acc[(2*g+1)*4 + 0], qp.y, d0);
                FMA2(acc[(2*g+1)*4 + 1], qp.y, d1);
                FMA2(acc[(2*g+1)*4 + 2], qp.y, d2);
                FMA2(acc[(2*g+1)*4 + 3], qp.y, d3);
            }
        }

        // exp + store to p_s (no max subtraction needed: |scores| <~ 6)
        #pragma unroll
        for (int mp = 0; mp < 8; ++mp) {
            float lo[4], hi[4];
            #pragma unroll
            for (int lj = 0; lj < 4; ++lj) {
                unsigned int ul, uh;
                UNPACK2(ul, uh, acc[mp*4 + lj]);
                lo[lj] = __expf(__uint_as_float(ul));
                hi[lj] = __expf(__uint_as_float(uh));
            }
            p_s4[(2*mp  )*CH4 + tid] = make_float4(lo[0], lo[1], lo[2], lo[3]);
            p_s4[(2*mp+1)*CH4 + tid] = make_float4(hi[0], hi[1], hi[2], hi[3]);
        }
    }
    __syncthreads();

    // ---------------- chunk sums (deterministic, warp w -> m=2w,2w+1) -------
    #pragma unroll
    for (int mm = 0; mm < 2; ++mm) {
        const int m = warp*2 + mm;
        float s = 0.f;
        for (int i = lane; i < CH4; i += 32) {
            const float4 v = p_s4[m*CH4 + i];
            s += (v.x + v.y) + (v.z + v.w);
        }
        #pragma unroll
        for (int off = 16; off; off >>= 1)
            s += __shfl_xor_sync(0xffffffffu, s, off);
        if (lane == 0) g_spart[(ch*NB + n)*MM + m] = s;
    }

    // ---------------- phase 2: partial fusion -------------------------------
    const ulonglong2* p_s8 = reinterpret_cast<const ulonglong2*>(p_s);
    float* fbase = g_fpart + (size_t)(ch*NB + n)*MM*CC;

    // reversed pass order: phase-1 just streamed high-c rows -> L2-warm
    for (int pass = 23; pass >= 0; --pass) {
        const int c0 = pass*16 + warp*2;
        unsigned long long acc[32];   // [m][cj] packed over (even l, odd l)
        #pragma unroll
        for (int i = 0; i < 32; ++i) acc[i] = 0ull;

        const float4* r0 = lf4 + (size_t)c0*L4;
        const float4* r1 = lf4 + (size_t)(c0+1)*L4;

        for (int s = 0; s < 6; ++s) {
            const int li = s*32 + lane;
            const float4 v0 = r0[li];
            const float4 v1 = r1[li];
            unsigned long long v0l, v0h, v1l, v1h;
            PACK2(v0l, v0.x, v0.y); PACK2(v0h, v0.z, v0.w);
            PACK2(v1l, v1.x, v1.y); PACK2(v1h, v1.z, v1.w);
            #pragma unroll
            for (int m = 0; m < MM; ++m) {
                const ulonglong2 pp = p_s8[m*CH4 + li];
                FMA2(acc[m*2+0], pp.x, v0l);
                FMA2(acc[m*2+0], pp.y, v0h);
                FMA2(acc[m*2+1], pp.x, v1l);
                FMA2(acc[m*2+1], pp.y, v1h);
            }
        }
        if (lane < 4) {                 // tail: li = 192..195
            const int li = 192 + lane;
            const float4 v0 = r0[li];
            const float4 v1 = r1[li];
            unsigned long long v0l, v0h, v1l, v1h;
            PACK2(v0l, v0.x, v0.y); PACK2(v0h, v0.z, v0.w);
            PACK2(v1l, v1.x, v1.y); PACK2(v1h, v1.z, v1.w);
            #pragma unroll
            for (int m = 0; m < MM; ++m) {
                const ulonglong2 pp = p_s8[m*CH4 + li];
                FMA2(acc[m*2+0], pp.x, v0l);
                FMA2(acc[m*2+0], pp.y, v0h);
                FMA2(acc[m*2+1], pp.x, v1l);
                FMA2(acc[m*2+1], pp.y, v1h);
            }
        }

        // horizontal add + warp reduce + write
        #pragma unroll
        for (int m = 0; m < MM; ++m) {
            #pragma unroll
            for (int cj = 0; cj < 2; ++cj) {
                unsigned int ul, uh;
                UNPACK2(ul, uh, acc[m*2+cj]);
                float r = __uint_as_float(ul) + __uint_as_float(uh);
                #pragma unroll
                for (int off = 16; off; off >>= 1)
                    r += __shfl_xor_sync(0xffffffffu, r, off);
                if (lane == 0) fbase[m*CC + c0 + cj] = r;
            }
        }
    }
}

// ---------------------------------------------------------------------------
// Kernel D: combine chunks + out[n,m,d] = f@Wu^T + bu + x
// ---------------------------------------------------------------------------
__global__ __launch_bounds__(256) void k_out(const float* __restrict__ x,
                                             const float* __restrict__ Wu,
                                             const float* __restrict__ bu,
                                             float* __restrict__ out) {
    const int n    = blockIdx.y;
    const int dblk = blockIdx.x * 32;
    const int tid  = threadIdx.x;
    const int warp = tid >> 5, lane = tid & 31;

    __shared__ float f_s[MM*CC];
    __shared__ float inv_s[MM];

    if (tid < MM) {
        float s = 0.f;
        #pragma unroll
        for (int k = 0; k < SCH; ++k) s += g_spart[(k*NB + n)*MM + tid];
        inv_s[tid] = 1.0f / s;
    }
    __syncthreads();

    for (int j = tid; j < MM*CC; j += 256) {
        float v = 0.f;
        #pragma unroll
        for (int k = 0; k < SCH; ++k)
            v += g_fpart[(size_t)(k*NB + n)*MM*CC + j];
        f_s[j] = v * inv_s[j / CC];     // f_s layout [m][c]
    }
    __syncthreads();
    const float4* fs4 = reinterpret_cast<const float4*>(f_s);

    for (int dd = 0; dd < 4; ++dd) {
        const int d = dblk + warp*4 + dd;
        const float4* wrow = reinterpret_cast<const float4*>(Wu + (size_t)d*CC);
        float acc[MM];
        #pragma unroll
        for (int m = 0; m < MM; ++m) acc[m] = 0.f;
        #pragma unroll
        for (int s = 0; s < 3; ++s) {
            const int c4 = s*32 + lane;
            const float4 wv = wrow[c4];
            #pragma unroll
            for (int m = 0; m < MM; ++m) {
                const float4 fv = fs4[m*96 + c4];
                acc[m] += wv.x*fv.x + wv.y*fv.y + wv.z*fv.z + wv.w*fv.w;
            }
        }
        #pragma unroll
        for (int m = 0; m < MM; ++m) {
            #pragma unroll
            for (int off = 16; off; off >>= 1)
                acc[m] += __shfl_xor_sync(0xffffffffu, acc[m], off);
        }
        if (lane == 0) {
            const float b = bu[d];
            #pragma unroll
            for (int m = 0; m < MM; ++m) {
                const int idx = n*MM*DD + m*DD + d;
                out[idx] = acc[m] + b + x[idx];
            }
        }
    }
}

// ---------------------------------------------------------------------------
extern "C" void kernel_launch(void* const* d_in, const int* in_sizes, int n_in,
                              void* d_out, int out_size) {
    const float* lf = (const float*)d_in[0];   // [64,384,56,56]
    const float* x  = (const float*)d_in[1];   // [64,16,384]
    const float* Wq = (const float*)d_in[2];   // [384,384]
    const float* bq = (const float*)d_in[3];   // [384]
    const float* Wu = (const float*)d_in[4];   // [384,384]
    const float* bu = (const float*)d_in[5];   // [384]
    float* out = (float*)d_out;                // [64,16,384]

    const int smem_attn = (MM*CHL + CC*MM) * (int)sizeof(float);  // 74752 B
    static int attr_done = 0;
    if (!attr_done) {
        cudaFuncSetAttribute(k_attn, cudaFuncAttributeMaxDynamicSharedMemorySize,
                             smem_attn);
        attr_done = 1;
    }

    k_q   <<<dim3(12, 64), 256>>>(x, Wq, bq);
    k_attn<<<dim3(SCH, 64), 256, smem_attn>>>(lf);
    k_out <<<dim3(12, 64), 256>>>(x, Wu, bu, out);
}

// round 14
// speedup vs baseline: 1.3732x; 1.3732x over previous
#include <cuda_runtime.h>
#include <math.h>

// Problem constants
#define NB 64
#define CC 384
#define LL 3136      // 56*56
#define MM 16
#define DD 384
#define L4 784       // LL/4 (float4 per lf row)

// Scratch (static device memory — no allocations)
__device__ float g_q[NB*MM*CC];     // scaled q, [n][m][c]
__device__ float g_p[NB*MM*LL];     // scores -> exp(scores - max), [n][m][l]
__device__ float g_isum[NB*MM];     // 1/rowsum
__device__ float g_f[NB*MM*CC];     // fusion (softmax-normalized), [n][m][c]

#define FMA4(A, s, V) { (A).x += (s)*(V).x; (A).y += (s)*(V).y; (A).z += (s)*(V).z; (A).w += (s)*(V).w; }
#define PREF_L1(p) asm volatile("prefetch.global.L1 [%0];" :: "l"(p))

// ---------------------------------------------------------------------------
// Kernel 0: q[n,m,c] = scale * (sum_d x[n,m,d]*Wq[c,d] + bq[c])
// grid (3, 64), 128 threads; thread owns one output column c, 16 m-accums.
// Wq row streams sequentially per thread (L1-friendly); x broadcast from smem.
// ---------------------------------------------------------------------------
__global__ __launch_bounds__(128) void k_q(const float* __restrict__ x,
                                           const float* __restrict__ Wq,
                                           const float* __restrict__ bq) {
    const int n = blockIdx.y;
    const int c = blockIdx.x * 128 + threadIdx.x;

    __shared__ float x_s[MM*DD];
    for (int j = threadIdx.x; j < MM*DD; j += 128) x_s[j] = x[n*MM*DD + j];
    __syncthreads();

    const float4* xs4  = reinterpret_cast<const float4*>(x_s);
    const float4* wrow = reinterpret_cast<const float4*>(Wq + (size_t)c*DD);

    float acc[MM];
    #pragma unroll
    for (int m = 0; m < MM; ++m) acc[m] = 0.f;

    #pragma unroll 2
    for (int d4 = 0; d4 < DD/4; ++d4) {
        const float4 w = wrow[d4];
        #pragma unroll
        for (int m = 0; m < MM; ++m) {
            const float4 xv = xs4[m*(DD/4) + d4];
            acc[m] += w.x*xv.x + w.y*xv.y + w.z*xv.z + w.w*xv.w;
        }
    }

    const float scale = 0.05103103630798287f;   // 384^-0.5
    const float b = bq[c];
    #pragma unroll
    for (int m = 0; m < MM; ++m)
        g_q[n*MM*CC + m*CC + c] = scale * (acc[m] + b);
}

// ---------------------------------------------------------------------------
// Kernel A: scores[n,m,l] = sum_c q[n,m,c] * lf[n,c,l]   (scale folded into q)
// grid (4, 64): CTA covers 1024 l's; thread owns 4 consecutive l (float4) and
// all 16 m accumulators. lf streamed coalesced along l; q transposed in smem.
// L1 prefetch 8 c-rows ahead to hide DRAM latency.
// ---------------------------------------------------------------------------
__global__ __launch_bounds__(256, 2) void k_scores(const float* __restrict__ lf) {
    const int n   = blockIdx.y;
    const int tid = threadIdx.x;
    const int l0  = blockIdx.x * 1024 + tid * 4;

    __shared__ float q_t[CC*MM];   // [c][m]
    for (int j = tid; j < MM*CC; j += 256) {
        const int m = j / CC, c = j % CC;
        q_t[c*MM + m] = g_q[n*MM*CC + j];
    }
    __syncthreads();
    if (l0 >= LL) return;

    const float4* qt4 = reinterpret_cast<const float4*>(q_t);
    float4 acc[MM];
    #pragma unroll
    for (int m = 0; m < MM; ++m) acc[m] = make_float4(0.f, 0.f, 0.f, 0.f);

    const float4* lfp = reinterpret_cast<const float4*>(lf) + (size_t)n*CC*L4 + (l0 >> 2);

    #pragma unroll 4
    for (int c = 0; c < CC; ++c) {
        const float4 v = lfp[(size_t)c * L4];   // lf[n, c, l0..l0+3]
        const int cp = (c + 8 < CC) ? c + 8 : c;
        PREF_L1(lfp + (size_t)cp * L4);
        #pragma unroll
        for (int mq = 0; mq < 4; ++mq) {
            const float4 qv = qt4[c*4 + mq];    // q for m = 4mq..4mq+3 (broadcast)
            FMA4(acc[4*mq+0], qv.x, v);
            FMA4(acc[4*mq+1], qv.y, v);
            FMA4(acc[4*mq+2], qv.z, v);
            FMA4(acc[4*mq+3], qv.w, v);
        }
    }

    float4* pout = reinterpret_cast<float4*>(g_p) + (size_t)n*MM*L4 + (l0 >> 2);
    #pragma unroll
    for (int m = 0; m < MM; ++m) pout[(size_t)m * L4] = acc[m];
}

// ---------------------------------------------------------------------------
// Kernel B: row softmax over l (3136). Writes exp(s - max) in place, 1/sum out.
// grid 1024 (= n*16+m rows), 256 threads.
// ---------------------------------------------------------------------------
__global__ __launch_bounds__(256) void k_softmax() {
    const int row  = blockIdx.x;
    float4* p4     = reinterpret_cast<float4*>(g_p) + (size_t)row * L4;
    const int tid  = threadIdx.x;
    const int warp = tid >> 5, lane = tid & 31;
    __shared__ float red[8];

    float mx = -3.4e38f;
    for (int i = tid; i < L4; i += 256) {
        const float4 v = p4[i];
        mx = fmaxf(mx, fmaxf(fmaxf(v.x, v.y), fmaxf(v.z, v.w)));
    }
    #pragma unroll
    for (int off = 16; off; off >>= 1)
        mx = fmaxf(mx, __shfl_xor_sync(0xffffffffu, mx, off));
    if (lane == 0) red[warp] = mx;
    __syncthreads();
    float m_all = red[0];
    #pragma unroll
    for (int k = 1; k < 8; ++k) m_all = fmaxf(m_all, red[k]);
    __syncthreads();

    float s = 0.f;
    for (int i = tid; i < L4; i += 256) {
        float4 v = p4[i];
        v.x = expf(v.x - m_all); v.y = expf(v.y - m_all);
        v.z = expf(v.z - m_all); v.w = expf(v.w - m_all);
        p4[i] = v;
        s += (v.x + v.y) + (v.z + v.w);
    }
    #pragma unroll
    for (int off = 16; off; off >>= 1)
        s += __shfl_xor_sync(0xffffffffu, s, off);
    if (lane == 0) red[warp] = s;
    __syncthreads();
    if (tid == 0) {
        float tot = 0.f;
        #pragma unroll
        for (int k = 0; k < 8; ++k) tot += red[k];
        g_isum[row] = 1.0f / tot;
    }
}

// ---------------------------------------------------------------------------
// Kernel C: f[n,m,c] = isum[n,m] * sum_l p[n,m,l] * lf[n,c,l]
// grid (12, 64): CTA = 32 c's; warp owns 4 c rows, lanes span l (coalesced LDG),
// p staged in smem tiles of 512 l. 64 fp32 accumulators/thread, shuffle-reduced.
// L1 prefetch of next s-step's lf lines (li+32 works across tile boundaries).
// ---------------------------------------------------------------------------
__global__ __launch_bounds__(256, 2) void k_fusion(const float* __restrict__ lf) {
    const int n    = blockIdx.y;
    const int tid  = threadIdx.x;
    const int warp = tid >> 5, lane = tid & 31;
    const int c0   = blockIdx.x * 32 + warp * 4;

    __shared__ float p_s[MM * 512];
    float4* ps4 = reinterpret_cast<float4*>(p_s);
    const float4* gp4 = reinterpret_cast<const float4*>(g_p) + (size_t)n*MM*L4;
    const float4* lf4 = reinterpret_cast<const float4*>(lf) + (size_t)n*CC*L4;

    float acc[64];
    #pragma unroll
    for (int i = 0; i < 64; ++i) acc[i] = 0.f;

    // warm the L1 with the first s-step's lines
    {
        const int li = lane;
        PREF_L1(lf4 + (size_t)(c0+0)*L4 + li);
        PREF_L1(lf4 + (size_t)(c0+1)*L4 + li);
        PREF_L1(lf4 + (size_t)(c0+2)*L4 + li);
        PREF_L1(lf4 + (size_t)(c0+3)*L4 + li);
    }

    // 6 full tiles of 512 l's
    for (int t = 0; t < 6; ++t) {
        __syncthreads();
        #pragma unroll
        for (int k = 0; k < 8; ++k) {
            const int j = tid + k*256;          // 0..2047 (16 rows x 128 float4)
            const int r = j >> 7, col = j & 127;
            ps4[j] = gp4[(size_t)r*L4 + t*128 + col];
        }
        __syncthreads();
        #pragma unroll
        for (int s = 0; s < 4; ++s) {
            const int li = t*128 + s*32 + lane;
            // prefetch next s-step (li+32 spans tile boundary correctly)
            const int lp = (li + 32 < L4) ? li + 32 : li;
            PREF_L1(lf4 + (size_t)(c0+0)*L4 + lp);
            PREF_L1(lf4 + (size_t)(c0+1)*L4 + lp);
            PREF_L1(lf4 + (size_t)(c0+2)*L4 + lp);
            PREF_L1(lf4 + (size_t)(c0+3)*L4 + lp);
            const float4 v0 = lf4[(size_t)(c0+0)*L4 + li];
            const float4 v1 = lf4[(size_t)(c0+1)*L4 + li];
            const float4 v2 = lf4[(size_t)(c0+2)*L4 + li];
            const float4 v3 = lf4[(size_t)(c0+3)*L4 + li];
            #pragma unroll
            for (int m = 0; m < MM; ++m) {
                const float4 pv = ps4[m*128 + s*32 + lane];
                acc[m*4+0] += pv.x*v0.x + pv.y*v0.y + pv.z*v0.z + pv.w*v0.w;
                acc[m*4+1] += pv.x*v1.x + pv.y*v1.y + pv.z*v1.z + pv.w*v1.w;
                acc[m*4+2] += pv.x*v2.x + pv.y*v2.y + pv.z*v2.z + pv.w*v2.w;
                acc[m*4+3] += pv.x*v3.x + pv.y*v3.y + pv.z*v3.z + pv.w*v3.w;
            }
        }
    }

    // tail: l in [3072, 3136) -> 16 float4 per row
    __syncthreads();
    {
        const int r = tid >> 4, col = tid & 15;
        ps4[r*128 + col] = gp4[(size_t)r*L4 + 768 + col];
    }
    __syncthreads();
    if (lane < 16) {
        const int li = 768 + lane;
        const float4 v0 = lf4[(size_t)(c0+0)*L4 + li];
        const float4 v1 = lf4[(size_t)(c0+1)*L4 + li];
        const float4 v2 = lf4[(size_t)(c0+2)*L4 + li];
        const float4 v3 = lf4[(size_t)(c0+3)*L4 + li];
        #pragma unroll
        for (int m = 0; m < MM; ++m) {
            const float4 pv = ps4[m*128 + lane];
            acc[m*4+0] += pv.x*v0.x + pv.y*v0.y + pv.z*v0.z + pv.w*v0.w;
            acc[m*4+1] += pv.x*v1.x + pv.y*v1.y + pv.z*v1.z + pv.w*v1.w;
            acc[m*4+2] += pv.x*v2.x + pv.y*v2.y + pv.z*v2.z + pv.w*v2.w;
            acc[m*4+3] += pv.x*v3.x + pv.y*v3.y + pv.z*v3.z + pv.w*v3.w;
        }
    }

    // warp reduce each of the 64 accumulators
    #pragma unroll
    for (int i = 0; i < 64; ++i) {
        float v = acc[i];
        #pragma unroll
        for (int off = 16; off; off >>= 1)
            v += __shfl_xor_sync(0xffffffffu, v, off);
        acc[i] = v;
    }
    if (lane == 0) {
        #pragma unroll
        for (int m = 0; m < MM; ++m) {
            const float inv = g_isum[n*MM + m];
            #pragma unroll
            for (int cc = 0; cc < 4; ++cc)
                g_f[n*MM*CC + m*CC + c0 + cc] = acc[m*4+cc] * inv;
        }
    }
}

// ---------------------------------------------------------------------------
// Kernel D: out[n,m,d] = sum_c f[n,m,c]*Wu[d,c] + bu[d] + x[n,m,d]
// Same lean structure as k_q: thread owns one d, 16 m-accums.
// ---------------------------------------------------------------------------
__global__ __launch_bounds__(128) void k_out(const float* __restrict__ x,
                                             const float* __restrict__ Wu,
                                             const float* __restrict__ bu,
                                             float* __restrict__ out) {
    const int n = blockIdx.y;
    const int d = blockIdx.x * 128 + threadIdx.x;

    __shared__ float f_s[MM*CC];
    for (int j = threadIdx.x; j < MM*CC; j += 128) f_s[j] = g_f[n*MM*CC + j];
    __syncthreads();

    const float4* fs4  = reinterpret_cast<const float4*>(f_s);
    const float4* wrow = reinterpret_cast<const float4*>(Wu + (size_t)d*CC);

    float acc[MM];
    #pragma unroll
    for (int m = 0; m < MM; ++m) acc[m] = 0.f;

    #pragma unroll 2
    for (int c4 = 0; c4 < CC/4; ++c4) {
        const float4 w = wrow[c4];
        #pragma unroll
        for (int m = 0; m < MM; ++m) {
            const float4 fv = fs4[m*(CC/4) + c4];
            acc[m] += w.x*fv.x + w.y*fv.y + w.z*fv.z + w.w*fv.w;
        }
    }

    const float b = bu[d];
    #pragma unroll
    for (int m = 0; m < MM; ++m) {
        const int idx = n*MM*DD + m*DD + d;
        out[idx] = acc[m] + b + x[idx];
    }
}

// ---------------------------------------------------------------------------
extern "C" void kernel_launch(void* const* d_in, const int* in_sizes, int n_in,
                              void* d_out, int out_size) {
    const float* lf = (const float*)d_in[0];   // [64,384,56,56]
    const float* x  = (const float*)d_in[1];   // [64,16,384]
    const float* Wq = (const float*)d_in[2];   // [384,384]
    const float* bq = (const float*)d_in[3];   // [384]
    const float* Wu = (const float*)d_in[4];   // [384,384]
    const float* bu = (const float*)d_in[5];   // [384]
    float* out = (float*)d_out;                // [64,16,384]

    k_q      <<<dim3(3,  64), 128>>>(x, Wq, bq);
    k_scores <<<dim3(4,  64), 256>>>(lf);
    k_softmax<<<1024,         256>>>();
    k_fusion <<<dim3(12, 64), 256>>>(lf);
    k_out    <<<dim3(3,  64), 128>>>(x, Wu, bu, out);
}

// round 15
// speedup vs baseline: 1.3815x; 1.0061x over previous
#include <cuda_runtime.h>
#include <math.h>

// Problem constants
#define NB 64
#define CC 384
#define LL 3136      // 56*56
#define MM 16
#define DD 384
#define L4 784       // LL/4 (float4 per lf row)

// Scratch (static device memory — no allocations)
__device__ float g_q[NB*MM*CC];     // scaled q, [n][m][c]
__device__ float g_p[NB*MM*LL];     // scores -> exp(scores - max), [n][m][l]
__device__ float g_isum[NB*MM];     // 1/rowsum
__device__ float g_f[NB*MM*CC];     // fusion (softmax-normalized), [n][m][c]

#define FMA4(A, s, V) { (A).x += (s)*(V).x; (A).y += (s)*(V).y; (A).z += (s)*(V).z; (A).w += (s)*(V).w; }
#define PREF_L1(p) asm volatile("prefetch.global.L1 [%0];" :: "l"(p))

// ---------------------------------------------------------------------------
// Kernel 0: q[n,m,c] = scale * (sum_d x[n,m,d]*Wq[c,d] + bq[c])
// grid (3, 64), 128 threads; thread owns one output column c, 16 m-accums.
// Wq row streams sequentially per thread (L1-friendly); x broadcast from smem.
// ---------------------------------------------------------------------------
__global__ __launch_bounds__(128) void k_q(const float* __restrict__ x,
                                           const float* __restrict__ Wq,
                                           const float* __restrict__ bq) {
    const int n = blockIdx.y;
    const int c = blockIdx.x * 128 + threadIdx.x;

    __shared__ float x_s[MM*DD];
    for (int j = threadIdx.x; j < MM*DD; j += 128) x_s[j] = x[n*MM*DD + j];
    __syncthreads();

    const float4* xs4  = reinterpret_cast<const float4*>(x_s);
    const float4* wrow = reinterpret_cast<const float4*>(Wq + (size_t)c*DD);

    float acc[MM];
    #pragma unroll
    for (int m = 0; m < MM; ++m) acc[m] = 0.f;

    #pragma unroll 2
    for (int d4 = 0; d4 < DD/4; ++d4) {
        const float4 w = wrow[d4];
        #pragma unroll
        for (int m = 0; m < MM; ++m) {
            const float4 xv = xs4[m*(DD/4) + d4];
            acc[m] += w.x*xv.x + w.y*xv.y + w.z*xv.z + w.w*xv.w;
        }
    }

    const float scale = 0.05103103630798287f;   // 384^-0.5
    const float b = bq[c];
    #pragma unroll
    for (int m = 0; m < MM; ++m)
        g_q[n*MM*CC + m*CC + c] = scale * (acc[m] + b);
}

// ---------------------------------------------------------------------------
// Kernel A: scores[n,m,l] = sum_c q[n,m,c] * lf[n,c,l]   (scale folded into q)
// grid (4, 64): CTA covers 1024 l's; thread owns 4 consecutive l (float4) and
// all 16 m accumulators. lf streamed coalesced along l; q transposed in smem.
// L1 prefetch 8 c-rows ahead to hide DRAM latency.
// ---------------------------------------------------------------------------
__global__ __launch_bounds__(256, 2) void k_scores(const float* __restrict__ lf) {
    const int n   = blockIdx.y;
    const int tid = threadIdx.x;
    const int l0  = blockIdx.x * 1024 + tid * 4;

    __shared__ float q_t[CC*MM];   // [c][m]
    for (int j = tid; j < MM*CC; j += 256) {
        const int m = j / CC, c = j % CC;
        q_t[c*MM + m] = g_q[n*MM*CC + j];
    }
    __syncthreads();
    if (l0 >= LL) return;

    const float4* qt4 = reinterpret_cast<const float4*>(q_t);
    float4 acc[MM];
    #pragma unroll
    for (int m = 0; m < MM; ++m) acc[m] = make_float4(0.f, 0.f, 0.f, 0.f);

    const float4* lfp = reinterpret_cast<const float4*>(lf) + (size_t)n*CC*L4 + (l0 >> 2);

    #pragma unroll 4
    for (int c = 0; c < CC; ++c) {
        const float4 v = lfp[(size_t)c * L4];   // lf[n, c, l0..l0+3]
        const int cp = (c + 8 < CC) ? c + 8 : c;
        PREF_L1(lfp + (size_t)cp * L4);
        #pragma unroll
        for (int mq = 0; mq < 4; ++mq) {
            const float4 qv = qt4[c*4 + mq];    // q for m = 4mq..4mq+3 (broadcast)
            FMA4(acc[4*mq+0], qv.x, v);
            FMA4(acc[4*mq+1], qv.y, v);
            FMA4(acc[4*mq+2], qv.z, v);
            FMA4(acc[4*mq+3], qv.w, v);
        }
    }

    float4* pout = reinterpret_cast<float4*>(g_p) + (size_t)n*MM*L4 + (l0 >> 2);
    #pragma unroll
    for (int m = 0; m < MM; ++m) pout[(size_t)m * L4] = acc[m];
}

// ---------------------------------------------------------------------------
// Kernel B: row softmax over l (3136). Writes exp(s - max) in place, 1/sum out.
// grid 1024 (= n*16+m rows), 256 threads.
// ---------------------------------------------------------------------------
__global__ __launch_bounds__(256) void k_softmax() {
    const int row  = blockIdx.x;
    float4* p4     = reinterpret_cast<float4*>(g_p) + (size_t)row * L4;
    const int tid  = threadIdx.x;
    const int warp = tid >> 5, lane = tid & 31;
    __shared__ float red[8];

    float mx = -3.4e38f;
    for (int i = tid; i < L4; i += 256) {
        const float4 v = p4[i];
        mx = fmaxf(mx, fmaxf(fmaxf(v.x, v.y), fmaxf(v.z, v.w)));
    }
    #pragma unroll
    for (int off = 16; off; off >>= 1)
        mx = fmaxf(mx, __shfl_xor_sync(0xffffffffu, mx, off));
    if (lane == 0) red[warp] = mx;
    __syncthreads();
    float m_all = red[0];
    #pragma unroll
    for (int k = 1; k < 8; ++k) m_all = fmaxf(m_all, red[k]);
    __syncthreads();

    float s = 0.f;
    for (int i = tid; i < L4; i += 256) {
        float4 v = p4[i];
        v.x = expf(v.x - m_all); v.y = expf(v.y - m_all);
        v.z = expf(v.z - m_all); v.w = expf(v.w - m_all);
        p4[i] = v;
        s += (v.x + v.y) + (v.z + v.w);
    }
    #pragma unroll
    for (int off = 16; off; off >>= 1)
        s += __shfl_xor_sync(0xffffffffu, s, off);
    if (lane == 0) red[warp] = s;
    __syncthreads();
    if (tid == 0) {
        float tot = 0.f;
        #pragma unroll
        for (int k = 0; k < 8; ++k) tot += red[k];
        g_isum[row] = 1.0f / tot;
    }
}

// ---------------------------------------------------------------------------
// Kernel C: f[n,m,c] = isum[n,m] * sum_l p[n,m,l] * lf[n,c,l]
// grid (12, 64): CTA = 32 c's; warp owns 4 c rows, lanes span l (coalesced LDG),
// p staged in smem tiles of 512 l. 64 fp32 accumulators/thread, shuffle-reduced.
// L1 prefetch of next s-step's lf lines (li+32 works across tile boundaries).
// ---------------------------------------------------------------------------
__global__ __launch_bounds__(256, 2) void k_fusion(const float* __restrict__ lf) {
    const int n    = blockIdx.y;
    const int tid  = threadIdx.x;
    const int warp = tid >> 5, lane = tid & 31;
    const int c0   = blockIdx.x * 32 + warp * 4;

    __shared__ float p_s[MM * 512];
    float4* ps4 = reinterpret_cast<float4*>(p_s);
    const float4* gp4 = reinterpret_cast<const float4*>(g_p) + (size_t)n*MM*L4;
    const float4* lf4 = reinterpret_cast<const float4*>(lf) + (size_t)n*CC*L4;

    float acc[64];
    #pragma unroll
    for (int i = 0; i < 64; ++i) acc[i] = 0.f;

    // warm the L1 with the first s-step's lines
    {
        const int li = lane;
        PREF_L1(lf4 + (size_t)(c0+0)*L4 + li);
        PREF_L1(lf4 + (size_t)(c0+1)*L4 + li);
        PREF_L1(lf4 + (size_t)(c0+2)*L4 + li);
        PREF_L1(lf4 + (size_t)(c0+3)*L4 + li);
    }

    // 6 full tiles of 512 l's
    for (int t = 0; t < 6; ++t) {
        __syncthreads();
        #pragma unroll
        for (int k = 0; k < 8; ++k) {
            const int j = tid + k*256;          // 0..2047 (16 rows x 128 float4)
            const int r = j >> 7, col = j & 127;
            ps4[j] = gp4[(size_t)r*L4 + t*128 + col];
        }
        __syncthreads();
        #pragma unroll
        for (int s = 0; s < 4; ++s) {
            const int li = t*128 + s*32 + lane;
            // prefetch next s-step (li+32 spans tile boundary correctly)
            const int lp = (li + 32 < L4) ? li + 32 : li;
            PREF_L1(lf4 + (size_t)(c0+0)*L4 + lp);
            PREF_L1(lf4 + (size_t)(c0+1)*L4 + lp);
            PREF_L1(lf4 + (size_t)(c0+2)*L4 + lp);
            PREF_L1(lf4 + (size_t)(c0+3)*L4 + lp);
            const float4 v0 = lf4[(size_t)(c0+0)*L4 + li];
            const float4 v1 = lf4[(size_t)(c0+1)*L4 + li];
            const float4 v2 = lf4[(size_t)(c0+2)*L4 + li];
            const float4 v3 = lf4[(size_t)(c0+3)*L4 + li];
            #pragma unroll
            for (int m = 0; m < MM; ++m) {
                const float4 pv = ps4[m*128 + s*32 + lane];
                acc[m*4+0] += pv.x*v0.x + pv.y*v0.y + pv.z*v0.z + pv.w*v0.w;
                acc[m*4+1] += pv.x*v1.x + pv.y*v1.y + pv.z*v1.z + pv.w*v1.w;
                acc[m*4+2] += pv.x*v2.x + pv.y*v2.y + pv.z*v2.z + pv.w*v2.w;
                acc[m*4+3] += pv.x*v3.x + pv.y*v3.y + pv.z*v3.z + pv.w*v3.w;
            }
        }
    }

    // tail: l in [3072, 3136) -> 16 float4 per row
    __syncthreads();
    {
        const int r = tid >> 4, col = tid & 15;
        ps4[r*128 + col] = gp4[(size_t)r*L4 + 768 + col];
    }
    __syncthreads();
    if (lane < 16) {
        const int li = 768 + lane;
        const float4 v0 = lf4[(size_t)(c0+0)*L4 + li];
        const float4 v1 = lf4[(size_t)(c0+1)*L4 + li];
        const float4 v2 = lf4[(size_t)(c0+2)*L4 + li];
        const float4 v3 = lf4[(size_t)(c0+3)*L4 + li];
        #pragma unroll
        for (int m = 0; m < MM; ++m) {
            const float4 pv = ps4[m*128 + lane];
            acc[m*4+0] += pv.x*v0.x + pv.y*v0.y + pv.z*v0.z + pv.w*v0.w;
            acc[m*4+1] += pv.x*v1.x + pv.y*v1.y + pv.z*v1.z + pv.w*v1.w;
            acc[m*4+2] += pv.x*v2.x + pv.y*v2.y + pv.z*v2.z + pv.w*v2.w;
            acc[m*4+3] += pv.x*v3.x + pv.y*v3.y + pv.z*v3.z + pv.w*v3.w;
        }
    }

    // warp reduce each of the 64 accumulators
    #pragma unroll
    for (int i = 0; i < 64; ++i) {
        float v = acc[i];
        #pragma unroll
        for (int off = 16; off; off >>= 1)
            v += __shfl_xor_sync(0xffffffffu, v, off);
        acc[i] = v;
    }
    if (lane == 0) {
        #pragma unroll
        for (int m = 0; m < MM; ++m) {
            const float inv = g_isum[n*MM + m];
            #pragma unroll
            for (int cc = 0; cc < 4; ++cc)
                g_f[n*MM*CC + m*CC + c0 + cc] = acc[m*4+cc] * inv;
        }
    }
}

// ---------------------------------------------------------------------------
// Kernel D: out[n,m,d] = sum_c f[n,m,c]*Wu[d,c] + bu[d] + x[n,m,d]
// Same lean structure as k_q: thread owns one d, 16 m-accums.
// ---------------------------------------------------------------------------
__global__ __launch_bounds__(128) void k_out(const float* __restrict__ x,
                                             const float* __restrict__ Wu,
                                             const float* __restrict__ bu,
                                             float* __restrict__ out) {
    const int n = blockIdx.y;
    const int d = blockIdx.x * 128 + threadIdx.x;

    __shared__ float f_s[MM*CC];
    for (int j = threadIdx.x; j < MM*CC; j += 128) f_s[j] = g_f[n*MM*CC + j];
    __syncthreads();

    const float4* fs4  = reinterpret_cast<const float4*>(f_s);
    const float4* wrow = reinterpret_cast<const float4*>(Wu + (size_t)d*CC);

    float acc[MM];
    #pragma unroll
    for (int m = 0; m < MM; ++m) acc[m] = 0.f;

    #pragma unroll 2
    for (int c4 = 0; c4 < CC/4; ++c4) {
        const float4 w = wrow[c4];
        #pragma unroll
        for (int m = 0; m < MM; ++m) {
            const float4 fv = fs4[m*(CC/4) + c4];
            acc[m] += w.x*fv.x + w.y*fv.y + w.z*fv.z + w.w*fv.w;
        }
    }

    const float b = bu[d];
    #pragma unroll
    for (int m = 0; m < MM; ++m) {
        const int idx = n*MM*DD + m*DD + d;
        out[idx] = acc[m] + b + x[idx];
    }
}

// ---------------------------------------------------------------------------
extern "C" void kernel_launch(void* const* d_in, const int* in_sizes, int n_in,
                              void* d_out, int out_size) {
    const float* lf = (const float*)d_in[0];   // [64,384,56,56]
    const float* x  = (const float*)d_in[1];   // [64,16,384]
    const float* Wq = (const float*)d_in[2];   // [384,384]
    const float* bq = (const float*)d_in[3];   // [384]
    const float* Wu = (const float*)d_in[4];   // [384,384]
    const float* bu = (const float*)d_in[5];   // [384]
    float* out = (float*)d_out;                // [64,16,384]

    k_q      <<<dim3(3,  64), 128>>>(x, Wq, bq);
    k_scores <<<dim3(4,  64), 256>>>(lf);
    k_softmax<<<1024,         256>>>();
    k_fusion <<<dim3(12, 64), 256>>>(lf);
    k_out    <<<dim3(3,  64), 128>>>(x, Wu, bu, out);
}

// round 16
// speedup vs baseline: 1.4288x; 1.0342x over previous
#include <cuda_runtime.h>
#include <math.h>

// Problem constants
#define NB 64
#define CC 384
#define LL 3136      // 56*56
#define MM 16
#define DD 384
#define L4 784       // LL/4 (float4 per lf row)

// scores tiling
#define LT   224     // l per scores CTA
#define NLB  14      // 3136/224
#define QP   388     // q_s row pitch (conflict-free a-frags)
#define LFP  232     // lf_s row pitch in scores (conflict-free b-frags)

// fusion tiling
#define FCH  112     // l per fusion chunk
#define NCH  28      // 3136/112
#define FP   116     // smem pitch in fusion (conflict-free a/b frags)

// Scratch (static device memory — no allocations)
__device__ float g_q[NB*MM*CC];        // scaled q, [n][m][c]
__device__ float g_p[NB*MM*LL];        // exp(scores), [n][m][l]
__device__ float g_spart[NLB*NB*MM];   // per-lblock exp sums
__device__ float g_f[NB*MM*CC];        // normalized fusion, [n][m][c]

#define CVT_TF32(o, i) asm("cvt.rna.tf32.f32 %0, %1;" : "=f"(o) : "f"(i))

__device__ __forceinline__ void mma_tf32(float& d0, float& d1, float& d2, float& d3,
                                         unsigned a0, unsigned a1, unsigned a2, unsigned a3,
                                         unsigned b0, unsigned b1) {
    asm("mma.sync.aligned.m16n8k8.row.col.f32.tf32.tf32.f32 "
        "{%0,%1,%2,%3}, {%4,%5,%6,%7}, {%8,%9}, {%0,%1,%2,%3};"
        : "+f"(d0), "+f"(d1), "+f"(d2), "+f"(d3)
        : "r"(a0), "r"(a1), "r"(a2), "r"(a3), "r"(b0), "r"(b1));
}

// ---------------------------------------------------------------------------
// Kernel 0: q[n,m,c] = scale * (sum_d x[n,m,d]*Wq[c,d] + bq[c])
// ---------------------------------------------------------------------------
__global__ __launch_bounds__(128) void k_q(const float* __restrict__ x,
                                           const float* __restrict__ Wq,
                                           const float* __restrict__ bq) {
    const int n = blockIdx.y;
    const int c = blockIdx.x * 128 + threadIdx.x;

    __shared__ float x_s[MM*DD];
    for (int j = threadIdx.x; j < MM*DD; j += 128) x_s[j] = x[n*MM*DD + j];
    __syncthreads();

    const float4* xs4  = reinterpret_cast<const float4*>(x_s);
    const float4* wrow = reinterpret_cast<const float4*>(Wq + (size_t)c*DD);

    float acc[MM];
    #pragma unroll
    for (int m = 0; m < MM; ++m) acc[m] = 0.f;

    #pragma unroll 2
    for (int d4 = 0; d4 < DD/4; ++d4) {
        const float4 w = wrow[d4];
        #pragma unroll
        for (int m = 0; m < MM; ++m) {
            const float4 xv = xs4[m*(DD/4) + d4];
            acc[m] += w.x*xv.x + w.y*xv.y + w.z*xv.z + w.w*xv.w;
        }
    }

    const float scale = 0.05103103630798287f;   // 384^-0.5
    const float b = bq[c];
    #pragma unroll
    for (int m = 0; m < MM; ++m)
        g_q[n*MM*CC + m*CC + c] = scale * (acc[m] + b);
}

// ---------------------------------------------------------------------------
// Kernel A (tensor): scores + exp + partial row sums.
// grid (NLB=14, 64), 224 threads (7 warps, warp = 32 l = 4 n-tiles of 8).
// D[16, 8] tf32 MMA, K over 384 c in 12 smem-staged blocks of 32.
// Epilogue: p = exp(score) -> g_p (float2 stores), partial sums -> g_spart.
// ---------------------------------------------------------------------------
__global__ __launch_bounds__(224) void k_scores(const float* __restrict__ lf) {
    extern __shared__ float sm[];
    float* q_s  = sm;                       // [16][QP]
    float* lf_s = sm + 16*QP;               // [32][LFP]
    float* red  = sm + 16*QP + 32*LFP;      // [7][16]

    const int n    = blockIdx.y;
    const int lb   = blockIdx.x;
    const int tid  = threadIdx.x;
    const int warp = tid >> 5;
    const int tg   = tid & 3;               // threadID in group (k index)
    const int gid  = (tid & 31) >> 2;       // group id (m / n index)

    // stage q with tf32 rounding
    for (int j = tid; j < MM*CC; j += 224) {
        const int m = j / CC, c = j % CC;
        float t; CVT_TF32(t, g_q[n*MM*CC + j]);
        q_s[m*QP + c] = t;
    }

    float d[4][4];
    #pragma unroll
    for (int t = 0; t < 4; ++t) { d[t][0]=0.f; d[t][1]=0.f; d[t][2]=0.f; d[t][3]=0.f; }

    const float4* lfg = reinterpret_cast<const float4*>(lf)
                        + (size_t)n*CC*L4 + lb*(LT/4);

    for (int cb = 0; cb < 12; ++cb) {
        __syncthreads();
        // stage lf rows c = cb*32..+31, 224 cols (56 float4 per row)
        for (int j = tid; j < 32*56; j += 224) {
            const int r = j / 56, c4 = j % 56;
            const float4 v = lfg[(size_t)(cb*32 + r)*L4 + c4];
            float4 t;
            CVT_TF32(t.x, v.x); CVT_TF32(t.y, v.y);
            CVT_TF32(t.z, v.z); CVT_TF32(t.w, v.w);
            *reinterpret_cast<float4*>(&lf_s[r*LFP + c4*4]) = t;
        }
        __syncthreads();

        #pragma unroll
        for (int kk = 0; kk < 4; ++kk) {
            const int cg = cb*32 + kk*8;   // global c base for this k-step
            const unsigned a0 = __float_as_uint(q_s[ gid     *QP + cg + tg    ]);
            const unsigned a1 = __float_as_uint(q_s[(gid + 8)*QP + cg + tg    ]);
            const unsigned a2 = __float_as_uint(q_s[ gid     *QP + cg + tg + 4]);
            const unsigned a3 = __float_as_uint(q_s[(gid + 8)*QP + cg + tg + 4]);
            #pragma unroll
            for (int t = 0; t < 4; ++t) {
                const int lcol = warp*32 + t*8 + gid;
                const unsigned b0 = __float_as_uint(lf_s[(kk*8 + tg    )*LFP + lcol]);
                const unsigned b1 = __float_as_uint(lf_s[(kk*8 + tg + 4)*LFP + lcol]);
                mma_tf32(d[t][0], d[t][1], d[t][2], d[t][3], a0, a1, a2, a3, b0, b1);
            }
        }
    }

    // epilogue: exp, coalesced-ish float2 stores, partial sums
    float sum_lo = 0.f, sum_hi = 0.f;
    float* prow_lo = g_p + ((size_t)n*MM + gid    )*LL;
    float* prow_hi = g_p + ((size_t)n*MM + gid + 8)*LL;
    #pragma unroll
    for (int t = 0; t < 4; ++t) {
        const int l = lb*LT + warp*32 + t*8 + 2*tg;
        const float e0 = __expf(d[t][0]), e1 = __expf(d[t][1]);
        const float e2 = __expf(d[t][2]), e3 = __expf(d[t][3]);
        *reinterpret_cast<float2*>(prow_lo + l) = make_float2(e0, e1);
        *reinterpret_cast<float2*>(prow_hi + l) = make_float2(e2, e3);
        sum_lo += e0 + e1;
        sum_hi += e2 + e3;
    }
    // reduce over the 4 lanes of each group (lanes differ only in low 2 bits)
    sum_lo += __shfl_xor_sync(0xffffffffu, sum_lo, 1);
    sum_lo += __shfl_xor_sync(0xffffffffu, sum_lo, 2);
    sum_hi += __shfl_xor_sync(0xffffffffu, sum_hi, 1);
    sum_hi += __shfl_xor_sync(0xffffffffu, sum_hi, 2);
    if (tg == 0) {
        red[warp*16 + gid    ] = sum_lo;
        red[warp*16 + gid + 8] = sum_hi;
    }
    __syncthreads();
    if (tid < 16) {
        float s = 0.f;
        #pragma unroll
        for (int w = 0; w < 7; ++w) s += red[w*16 + tid];
        g_spart[(lb*NB + n)*MM + tid] = s;
    }
}

// ---------------------------------------------------------------------------
// Kernel C (tensor): f[n,m,c] = (1/sum) * sum_l p[m,l] * lf[c,l]
// grid (6, 64) = 384 CTAs (single wave), 256 threads; warp owns one 8-c tile.
// 28 chunks of 112 l staged in smem; D accumulates over all 3136 l in regs.
// ---------------------------------------------------------------------------
__global__ __launch_bounds__(256) void k_fusion(const float* __restrict__ lf) {
    __shared__ float lf_s[64*FP];
    __shared__ float p_s[16*FP];
    __shared__ float inv_s[MM];

    const int n    = blockIdx.y;
    const int cblk = blockIdx.x;            // 6 blocks of 64 c
    const int tid  = threadIdx.x;
    const int warp = tid >> 5;
    const int tg   = tid & 3;
    const int gid  = (tid & 31) >> 2;

    if (tid < MM) {
        float s = 0.f;
        #pragma unroll
        for (int lb = 0; lb < NLB; ++lb) s += g_spart[(lb*NB + n)*MM + tid];
        inv_s[tid] = 1.0f / s;
    }

    float d0 = 0.f, d1 = 0.f, d2 = 0.f, d3 = 0.f;

    const float4* lfg = reinterpret_cast<const float4*>(lf) + (size_t)n*CC*L4;
    const float4* pg  = reinterpret_cast<const float4*>(g_p) + (size_t)n*MM*L4;

    for (int ch = 0; ch < NCH; ++ch) {
        __syncthreads();
        // stage lf: 64 rows (c) x 28 float4 = 1792
        #pragma unroll
        for (int k = 0; k < 7; ++k) {
            const int j = tid + k*256;
            const int r = j / 28, c4 = j % 28;
            const float4 v = lfg[(size_t)(cblk*64 + r)*L4 + ch*28 + c4];
            float4 t;
            CVT_TF32(t.x, v.x); CVT_TF32(t.y, v.y);
            CVT_TF32(t.z, v.z); CVT_TF32(t.w, v.w);
            *reinterpret_cast<float4*>(&lf_s[r*FP + c4*4]) = t;
        }
        // stage p: 16 rows (m) x 28 float4 = 448
        for (int j = tid; j < 448; j += 256) {
            const int r = j / 28, c4 = j % 28;
            const float4 v = pg[(size_t)r*L4 + ch*28 + c4];
            float4 t;
            CVT_TF32(t.x, v.x); CVT_TF32(t.y, v.y);
            CVT_TF32(t.z, v.z); CVT_TF32(t.w, v.w);
            *reinterpret_cast<float4*>(&p_s[r*FP + c4*4]) = t;
        }
        __syncthreads();

        #pragma unroll
        for (int kk = 0; kk < 14; ++kk) {
            const int lk = kk*8;
            const unsigned a0 = __float_as_uint(p_s[ gid     *FP + lk + tg    ]);
            const unsigned a1 = __float_as_uint(p_s[(gid + 8)*FP + lk + tg    ]);
            const unsigned a2 = __float_as_uint(p_s[ gid     *FP + lk + tg + 4]);
            const unsigned a3 = __float_as_uint(p_s[(gid + 8)*FP + lk + tg + 4]);
            const unsigned b0 = __float_as_uint(lf_s[(warp*8 + gid)*FP + lk + tg    ]);
            const unsigned b1 = __float_as_uint(lf_s[(warp*8 + gid)*FP + lk + tg + 4]);
            mma_tf32(d0, d1, d2, d3, a0, a1, a2, a3, b0, b1);
        }
    }

    const float inv_lo = inv_s[gid], inv_hi = inv_s[gid + 8];
    const int c = cblk*64 + warp*8 + 2*tg;
    float* frow_lo = g_f + ((size_t)n*MM + gid    )*CC;
    float* frow_hi = g_f + ((size_t)n*MM + gid + 8)*CC;
    *reinterpret_cast<float2*>(frow_lo + c) = make_float2(d0*inv_lo, d1*inv_lo);
    *reinterpret_cast<float2*>(frow_hi + c) = make_float2(d2*inv_hi, d3*inv_hi);
}

// ---------------------------------------------------------------------------
// Kernel D: out[n,m,d] = sum_c f[n,m,c]*Wu[d,c] + bu[d] + x[n,m,d]
// ---------------------------------------------------------------------------
__global__ __launch_bounds__(128) void k_out(const float* __restrict__ x,
                                             const float* __restrict__ Wu,
                                             const float* __restrict__ bu,
                                             float* __restrict__ out) {
    const int n = blockIdx.y;
    const int d = blockIdx.x * 128 + threadIdx.x;

    __shared__ float f_s[MM*CC];
    for (int j = threadIdx.x; j < MM*CC; j += 128) f_s[j] = g_f[n*MM*CC + j];
    __syncthreads();

    const float4* fs4  = reinterpret_cast<const float4*>(f_s);
    const float4* wrow = reinterpret_cast<const float4*>(Wu + (size_t)d*CC);

    float acc[MM];
    #pragma unroll
    for (int m = 0; m < MM; ++m) acc[m] = 0.f;

    #pragma unroll 2
    for (int c4 = 0; c4 < CC/4; ++c4) {
        const float4 w = wrow[c4];
        #pragma unroll
        for (int m = 0; m < MM; ++m) {
            const float4 fv = fs4[m*(CC/4) + c4];
            acc[m] += w.x*fv.x + w.y*fv.y + w.z*fv.z + w.w*fv.w;
        }
    }

    const float b = bu[d];
    #pragma unroll
    for (int m = 0; m < MM; ++m) {
        const int idx = n*MM*DD + m*DD + d;
        out[idx] = acc[m] + b + x[idx];
    }
}

// ---------------------------------------------------------------------------
extern "C" void kernel_launch(void* const* d_in, const int* in_sizes, int n_in,
                              void* d_out, int out_size) {
    const float* lf = (const float*)d_in[0];   // [64,384,56,56]
    const float* x  = (const float*)d_in[1];   // [64,16,384]
    const float* Wq = (const float*)d_in[2];   // [384,384]
    const float* bq = (const float*)d_in[3];   // [384]
    const float* Wu = (const float*)d_in[4];   // [384,384]
    const float* bu = (const float*)d_in[5];   // [384]
    float* out = (float*)d_out;                // [64,16,384]

    const int smem_scores = (16*QP + 32*LFP + 7*16) * (int)sizeof(float); // ~55 KB
    static int attr_done = 0;
    if (!attr_done) {
        cudaFuncSetAttribute(k_scores, cudaFuncAttributeMaxDynamicSharedMemorySize,
                             smem_scores);
        attr_done = 1;
    }

    k_q     <<<dim3(3,   64), 128>>>(x, Wq, bq);
    k_scores<<<dim3(NLB, 64), 224, smem_scores>>>(lf);
    k_fusion<<<dim3(6,   64), 256>>>(lf);
    k_out   <<<dim3(3,   64), 128>>>(x, Wu, bu, out);
}